// round 17
// baseline (speedup 1.0000x reference)
#include <cuda_runtime.h>
#include <cuda_bf16.h>
#include <cuda_fp8.h>
#include <math.h>

#define B_ 16
#define N_ 1024
#define D_ 128
#define L_ 4
#define BN_ (B_*N_)
#define EMAX (1<<22)

typedef __nv_bfloat16 bf16;
typedef __nv_bfloat162 bf162;

__device__ __align__(128) float g_h [BN_*D_];
__device__ __align__(128) float g_hh[BN_*D_];
__device__ __align__(128) float g_hA[BN_*D_];
__device__ __align__(128) bf16  g_hhb[BN_*D_];
__device__ __align__(128) bf16  g_hAb[BN_*D_];
__device__ __align__(128) unsigned char g_hh8[BN_*D_];
__device__ __align__(128) unsigned char g_z8[4][BN_*D_];
__device__ __align__(128) bf16  g_azb[2][BN_*D_];
__device__ __align__(128) float g_zA[BN_*D_];
__device__ __align__(128) float g_zC[BN_*D_];
__device__ __align__(128) float g_cf[2*BN_];
__device__ __align__(128) float g_pool[B_*D_];
__device__ __align__(128) int   g_rowptr[2][BN_ + 1];
__device__ __align__(128) int   g_us[2][BN_];
__device__ __align__(128) int   g_col[2][EMAX];
__device__ __align__(128) int   g_mir[2][EMAX];
__device__ __align__(128) float g_ev[2][EMAX];
__device__ __align__(128) float g_av[2][EMAX];
__device__ __align__(128) float g_invs[2*BN_];

// ---------- bf16 helpers ----------
__device__ __forceinline__ float4 ldz4(const bf16* p) {
    uint2 raw = *(const uint2*)p;
    bf162 lo = *reinterpret_cast<bf162*>(&raw.x);
    bf162 hi = *reinterpret_cast<bf162*>(&raw.y);
    float2 f0 = __bfloat1622float2(lo);
    float2 f1 = __bfloat1622float2(hi);
    return make_float4(f0.x, f0.y, f1.x, f1.y);
}
__device__ __forceinline__ void stz4(bf16* p, float4 v) {
    bf162 a = __floats2bfloat162_rn(v.x, v.y);
    bf162 b = __floats2bfloat162_rn(v.z, v.w);
    uint2 r;
    r.x = *reinterpret_cast<unsigned*>(&a);
    r.y = *reinterpret_cast<unsigned*>(&b);
    *(uint2*)p = r;
}
// ---------- fp8 e4m3 helpers (4 values in 4 bytes) ----------
__device__ __forceinline__ float4 ldq4(const unsigned char* p) {
    const unsigned raw = *(const unsigned*)p;
    __half2_raw h0 = __nv_cvt_fp8x2_to_halfraw2((__nv_fp8x2_storage_t)(raw & 0xFFFFu), __NV_E4M3);
    __half2_raw h1 = __nv_cvt_fp8x2_to_halfraw2((__nv_fp8x2_storage_t)(raw >> 16), __NV_E4M3);
    float2 f0 = __half22float2(*reinterpret_cast<__half2*>(&h0));
    float2 f1 = __half22float2(*reinterpret_cast<__half2*>(&h1));
    return make_float4(f0.x, f0.y, f1.x, f1.y);
}
__device__ __forceinline__ void stq4(unsigned char* p, float4 v) {
    __nv_fp8x2_storage_t lo = __nv_cvt_float2_to_fp8x2(make_float2(v.x, v.y), __NV_SATFINITE, __NV_E4M3);
    __nv_fp8x2_storage_t hi = __nv_cvt_float2_to_fp8x2(make_float2(v.z, v.w), __NV_SATFINITE, __NV_E4M3);
    *(unsigned*)p = (unsigned)lo | ((unsigned)hi << 16);
}

// ============ embede SGEMM: 64x128 tile, 4x8/thread (TRANSB) ============
__global__ void __launch_bounds__(256)
sgemm_e_k(const float* __restrict__ Ag, const float* __restrict__ Bg,
          float* __restrict__ Cg, int K)
{
    __shared__ float As[16][68];
    __shared__ float Bs[16][132];
    const int tid = threadIdx.x;
    const int tx = tid & 15, ty = tid >> 4;
    const int mbase = blockIdx.x * 64;

    const int arow  = tid >> 2;
    const int akoff = (tid & 3) * 4;
    const float* aptr = Ag + (size_t)(mbase + arow) * K + akoff;
    const int bn = tid & 127, bkh = (tid >> 7) * 8;
    const float* bptr = Bg + (size_t)bn * K + bkh;

    float acc[4][8];
#pragma unroll
    for (int i = 0; i < 4; i++)
#pragma unroll
        for (int j = 0; j < 8; j++) acc[i][j] = 0.f;

    const int nk = K >> 4;
    for (int kc = 0; kc < nk; ++kc) {
        float4 pa  = *(const float4*)(aptr + kc * 16);
        float4 pb0 = *(const float4*)(bptr + kc * 16);
        float4 pb1 = *(const float4*)(bptr + kc * 16 + 4);
        As[akoff+0][arow]=pa.x; As[akoff+1][arow]=pa.y;
        As[akoff+2][arow]=pa.z; As[akoff+3][arow]=pa.w;
        Bs[bkh+0][bn]=pb0.x; Bs[bkh+1][bn]=pb0.y;
        Bs[bkh+2][bn]=pb0.z; Bs[bkh+3][bn]=pb0.w;
        Bs[bkh+4][bn]=pb1.x; Bs[bkh+5][bn]=pb1.y;
        Bs[bkh+6][bn]=pb1.z; Bs[bkh+7][bn]=pb1.w;
        __syncthreads();
#pragma unroll
        for (int kk = 0; kk < 16; ++kk) {
            float4 av0 = *(const float4*)&As[kk][ty*4];
            float4 bv0 = *(const float4*)&Bs[kk][tx*8];
            float4 bv1 = *(const float4*)&Bs[kk][tx*8+4];
            float ar[4] = {av0.x,av0.y,av0.z,av0.w};
            float br[8] = {bv0.x,bv0.y,bv0.z,bv0.w,bv1.x,bv1.y,bv1.z,bv1.w};
#pragma unroll
            for (int i = 0; i < 4; i++)
#pragma unroll
                for (int j = 0; j < 8; j++)
                    acc[i][j] += ar[i] * br[j];
        }
        __syncthreads();
    }
    const int row0 = mbase + ty * 4;
    const int col0 = tx * 8;
#pragma unroll
    for (int i = 0; i < 4; i++) {
        float4* cp = (float4*)(Cg + (size_t)(row0 + i) * D_ + col0);
        cp[0] = make_float4(acc[i][0], acc[i][1], acc[i][2], acc[i][3]);
        cp[1] = make_float4(acc[i][4], acc[i][5], acc[i][6], acc[i][7]);
    }
}

// ===== fused: hh = h@W^T + b (f32+bf16+fp8), hA = hh@A (f32+bf16) ===
__global__ void __launch_bounds__(256)
hhA_k(const float* __restrict__ h, const float* __restrict__ W,
      const float* __restrict__ A, const float* __restrict__ bias,
      float* __restrict__ hh, bf16* __restrict__ hhb,
      unsigned char* __restrict__ hh8,
      float* __restrict__ hA, bf16* __restrict__ hAb)
{
    __shared__ float As[16][68];
    __shared__ float Bs[16][132];
    __shared__ float hhs[64][132];
    const int tid = threadIdx.x;
    const int tx = tid & 15, ty = tid >> 4;
    const int mbase = blockIdx.x * 64;

    const int arow  = tid >> 2;
    const int akoff = (tid & 3) * 4;
    const float* aptr = h + (size_t)(mbase + arow) * D_ + akoff;
    const int bn = tid & 127, bkh = (tid >> 7) * 8;
    const float* wptr = W + (size_t)bn * D_ + bkh;

    float acc[4][8];
#pragma unroll
    for (int i = 0; i < 4; i++)
#pragma unroll
        for (int j = 0; j < 8; j++) acc[i][j] = 0.f;

#pragma unroll 1
    for (int kc = 0; kc < 8; ++kc) {
        float4 pa  = *(const float4*)(aptr + kc * 16);
        float4 pb0 = *(const float4*)(wptr + kc * 16);
        float4 pb1 = *(const float4*)(wptr + kc * 16 + 4);
        As[akoff+0][arow]=pa.x; As[akoff+1][arow]=pa.y;
        As[akoff+2][arow]=pa.z; As[akoff+3][arow]=pa.w;
        Bs[bkh+0][bn]=pb0.x; Bs[bkh+1][bn]=pb0.y;
        Bs[bkh+2][bn]=pb0.z; Bs[bkh+3][bn]=pb0.w;
        Bs[bkh+4][bn]=pb1.x; Bs[bkh+5][bn]=pb1.y;
        Bs[bkh+6][bn]=pb1.z; Bs[bkh+7][bn]=pb1.w;
        __syncthreads();
#pragma unroll
        for (int kk = 0; kk < 16; ++kk) {
            float4 av0 = *(const float4*)&As[kk][ty*4];
            float4 bv0 = *(const float4*)&Bs[kk][tx*8];
            float4 bv1 = *(const float4*)&Bs[kk][tx*8+4];
            float ar[4] = {av0.x,av0.y,av0.z,av0.w};
            float br[8] = {bv0.x,bv0.y,bv0.z,bv0.w,bv1.x,bv1.y,bv1.z,bv1.w};
#pragma unroll
            for (int i = 0; i < 4; i++)
#pragma unroll
                for (int j = 0; j < 8; j++)
                    acc[i][j] += ar[i] * br[j];
        }
        __syncthreads();
    }

    const int row0 = ty * 4;
    const int col0 = tx * 8;
#pragma unroll
    for (int i = 0; i < 4; i++) {
        float o[8];
#pragma unroll
        for (int j = 0; j < 8; j++) {
            o[j] = acc[i][j] + bias[col0 + j];
            hhs[row0 + i][col0 + j] = o[j];
            acc[i][j] = 0.f;
        }
        const size_t go = (size_t)(mbase + row0 + i) * D_ + col0;
        const float4 lo = make_float4(o[0], o[1], o[2], o[3]);
        const float4 hi = make_float4(o[4], o[5], o[6], o[7]);
        *(float4*)(hh + go)     = lo;
        *(float4*)(hh + go + 4) = hi;
        stz4(hhb + go,     lo);
        stz4(hhb + go + 4, hi);
        stq4(hh8 + go,     lo);
        stq4(hh8 + go + 4, hi);
    }
    __syncthreads();

    const int bkr = tid >> 4, bcoff = (tid & 15) * 8;
#pragma unroll 1
    for (int kc = 0; kc < 8; ++kc) {
        const float* ap = A + (size_t)(kc * 16 + bkr) * D_ + bcoff;
        float4 pb0 = *(const float4*)ap;
        float4 pb1 = *(const float4*)(ap + 4);
        *(float4*)&Bs[bkr][bcoff]   = pb0;
        *(float4*)&Bs[bkr][bcoff+4] = pb1;
        __syncthreads();
#pragma unroll
        for (int kk = 0; kk < 16; ++kk) {
            float4 bv0 = *(const float4*)&Bs[kk][tx*8];
            float4 bv1 = *(const float4*)&Bs[kk][tx*8+4];
            float br[8] = {bv0.x,bv0.y,bv0.z,bv0.w,bv1.x,bv1.y,bv1.z,bv1.w};
#pragma unroll
            for (int i = 0; i < 4; i++) {
                const float a = hhs[row0 + i][kc * 16 + kk];
#pragma unroll
                for (int j = 0; j < 8; j++)
                    acc[i][j] += a * br[j];
            }
        }
        __syncthreads();
    }
#pragma unroll
    for (int i = 0; i < 4; i++) {
        const size_t go = (size_t)(mbase + row0 + i) * D_ + col0;
        const float4 lo = make_float4(acc[i][0], acc[i][1], acc[i][2], acc[i][3]);
        const float4 hi = make_float4(acc[i][4], acc[i][5], acc[i][6], acc[i][7]);
        *(float4*)(hA + go)     = lo;
        *(float4*)(hA + go + 4) = hi;
        stz4(hAb + go,     lo);
        stz4(hAb + go + 4, hi);
    }
}

// ============ CSR build (dual-adj via blockIdx.y) ============
__global__ void deg_k(const float* __restrict__ a0, const float* __restrict__ a1,
                      int* __restrict__ rp0, int* __restrict__ rp1)
{
    const float* adj = blockIdx.y ? a1 : a0;
    int* rp = blockIdx.y ? rp1 : rp0;
    const int wid = (blockIdx.x * blockDim.x + threadIdx.x) >> 5;
    const int lane = threadIdx.x & 31;
    if (wid >= BN_) return;
    const float* row = adj + (size_t)wid * N_;
    int c = 0;
#pragma unroll 4
    for (int k = 0; k < 32; k++) c += (row[lane + k * 32] > 0.f) ? 1 : 0;
    for (int o = 16; o; o >>= 1) c += __shfl_xor_sync(0xFFFFFFFFu, c, o);
    if (lane == 0) rp[wid + 1] = c;
}

__global__ void scan_k(int* __restrict__ rp0, int* __restrict__ rp1)
{
    int* rp = blockIdx.x ? rp1 : rp0;
    __shared__ int part[1024];
    const int t = threadIdx.x;
    int loc[16];
    int run = 0;
#pragma unroll
    for (int k = 0; k < 16; k++) { run += rp[1 + t * 16 + k]; loc[k] = run; }
    part[t] = run;
    __syncthreads();
    for (int off = 1; off < 1024; off <<= 1) {
        int v = (t >= off) ? part[t - off] : 0;
        __syncthreads();
        part[t] += v;
        __syncthreads();
    }
    const int excl = (t == 0) ? 0 : part[t - 1];
#pragma unroll
    for (int k = 0; k < 16; k++) rp[1 + t * 16 + k] = excl + loc[k];
    if (t == 0) rp[0] = 0;
}

__global__ void fill_k(const float* __restrict__ a0, const float* __restrict__ a1,
                       const int* __restrict__ rp0, const int* __restrict__ rp1,
                       int* __restrict__ col0, int* __restrict__ col1)
{
    const float* adj = blockIdx.y ? a1 : a0;
    const int* rp = blockIdx.y ? rp1 : rp0;
    int* col = blockIdx.y ? col1 : col0;
    const int wid = (blockIdx.x * blockDim.x + threadIdx.x) >> 5;
    const int lane = threadIdx.x & 31;
    if (wid >= BN_) return;
    const float* row = adj + (size_t)wid * N_;
    const int c0 = lane * 32;
    int cnt = 0;
#pragma unroll 4
    for (int k = 0; k < 32; k++) cnt += (row[c0 + k] > 0.f) ? 1 : 0;
    int inc = cnt;
    for (int off = 1; off < 32; off <<= 1) {
        int v = __shfl_up_sync(0xFFFFFFFFu, inc, off);
        if (lane >= off) inc += v;
    }
    int pos = rp[wid] + (inc - cnt);
    for (int k = 0; k < 32; k++)
        if (row[c0 + k] > 0.f) col[pos++] = c0 + k;
}

__global__ void mirror_k(const int* __restrict__ rp0, const int* __restrict__ col0,
                         int* __restrict__ mir0, int* __restrict__ us0,
                         const int* __restrict__ rp1, const int* __restrict__ col1,
                         int* __restrict__ mir1, int* __restrict__ us1)
{
    const int* rp  = blockIdx.y ? rp1  : rp0;
    const int* col = blockIdx.y ? col1 : col0;
    int* mir = blockIdx.y ? mir1 : mir0;
    int* us  = blockIdx.y ? us1  : us0;
    const int wid = (blockIdx.x * blockDim.x + threadIdx.x) >> 5;
    const int lane = threadIdx.x & 31;
    if (wid >= BN_) return;
    const int i = wid & (N_ - 1);
    const int bN = wid - i;
    const int rs = rp[wid], re = rp[wid + 1];
    for (int e = rs + lane; e < re; e += 32) {
        const int j = col[e];
        if (j == i) us[wid] = e;
        int lo = rp[bN + j], hi = rp[bN + j + 1];
        while (lo < hi) {
            int mid = (lo + hi) >> 1;
            if (col[mid] < i) lo = mid + 1; else hi = mid;
        }
        mir[e] = lo;
    }
}

// ===== edge logits: block-per-row, i-side fp32 smem, bf16 j-gather ======
__global__ void __launch_bounds__(128)
elog2_k(const float* __restrict__ hh, const float* __restrict__ hA,
        const bf16* __restrict__ hhb, const bf16* __restrict__ hAb,
        const int* __restrict__ rp0, const int* __restrict__ col0,
        const int* __restrict__ mir0, const int* __restrict__ us0,
        float* __restrict__ ev0,
        const int* __restrict__ rp1, const int* __restrict__ col1,
        const int* __restrict__ mir1, const int* __restrict__ us1,
        float* __restrict__ ev1)
{
    const int br = blockIdx.z;
    const int* rp  = br ? rp1  : rp0;
    const int* col = br ? col1 : col0;
    const int* mir = br ? mir1 : mir0;
    const int* us  = br ? us1  : us0;
    float*     ev  = br ? ev1  : ev0;

    __shared__ float shh[128], sha[128];
    const int i = blockIdx.x, b = blockIdx.y;
    const int r = b * N_ + i;
    const int t = threadIdx.x;
    shh[t] = hh[(size_t)r * D_ + t];
    sha[t] = hA[(size_t)r * D_ + t];
    __syncthreads();
    const int w = t >> 5, lane = t & 31;
    const int rs = us[r], re = rp[r + 1];
    const float4 a1 = *(const float4*)(sha + lane * 4);
    const float4 h1 = *(const float4*)(shh + lane * 4);
    for (int e = rs + w; e < re; e += 4) {
        const int j = col[e];
        const size_t jo = ((size_t)(b * N_ + j)) * D_ + lane * 4;
        const float4 h2 = ldz4(hhb + jo);
        const float4 a2 = ldz4(hAb + jo);
        float p = a1.x*h2.x + a1.y*h2.y + a1.z*h2.z + a1.w*h2.w
                + h1.x*a2.x + h1.y*a2.y + h1.z*a2.z + h1.w*a2.w;
        for (int o = 16; o; o >>= 1) p += __shfl_xor_sync(0xFFFFFFFFu, p, o);
        if (lane == 0) {
            const float x = __expf(p);
            ev[e] = x;
            ev[mir[e]] = x;
        }
    }
}

// ===== softmax denominators, both branches =====
__global__ void stats2_k(const int* __restrict__ rp0, const float* __restrict__ ev0,
                         const int* __restrict__ rp1, const float* __restrict__ ev1,
                         float* __restrict__ invs)
{
    const int u = blockIdx.x * 8 + (threadIdx.x >> 5);
    const int lane = threadIdx.x & 31;
    if (u >= 2 * BN_) return;
    const bool s1 = (u >= BN_);
    const int r = s1 ? u - BN_ : u;
    const int* rp = s1 ? rp1 : rp0;
    const float* ev = s1 ? ev1 : ev0;
    const int rs = rp[r], re = rp[r + 1];
    float s = 0.f;
    for (int e = rs + lane; e < re; e += 32) s += ev[e];
    for (int o = 16; o; o >>= 1) s += __shfl_xor_sync(0xFFFFFFFFu, s, o);
    if (lane == 0) invs[u] = 1.f / (s + (float)(N_ - (re - rs)));
}

// ===== fold column normalizer, both branches =====
__global__ void fold2_k(const int* __restrict__ rp0, const int* __restrict__ col0,
                        const float* __restrict__ ev0, float* __restrict__ av0,
                        const int* __restrict__ rp1, const int* __restrict__ col1,
                        const float* __restrict__ ev1, float* __restrict__ av1,
                        const float* __restrict__ invs)
{
    const int u = blockIdx.x * 8 + (threadIdx.x >> 5);
    const int lane = threadIdx.x & 31;
    if (u >= 2 * BN_) return;
    const bool s1 = (u >= BN_);
    const int r = s1 ? u - BN_ : u;
    const int* rp  = s1 ? rp1  : rp0;
    const int* col = s1 ? col1 : col0;
    const float* ev = s1 ? ev1 : ev0;
    float* av = s1 ? av1 : av0;
    const int ibase = (s1 ? BN_ : 0) + (r & ~(N_ - 1));
    const int rs = rp[r], re = rp[r + 1];
    for (int e = rs + lane; e < re; e += 32)
        av[e] = ev[e] * invs[ibase + col[e]];
}

// ============ SpMM: warp-per-row fp8 L2 gather, av stream ============
// Rows u in [0, 2BN): set0 if u<BN_, else set1.
// EPI 0: relu(acc) -> bf16 az.  EPI 1: c*hh+(1-c)*relu -> fp8.
// EPI 2: c*hh+(1-c)*relu -> fp32.
template<int EPI>
__global__ void __launch_bounds__(256)
spmm_k(const int* __restrict__ rp0, const int* __restrict__ col0,
       const float* __restrict__ av0,
       const int* __restrict__ rp1, const int* __restrict__ col1,
       const float* __restrict__ av1,
       const unsigned char* __restrict__ Z0, const unsigned char* __restrict__ Z1,
       bf16* __restrict__ outZ0, bf16* __restrict__ outZ1,
       unsigned char* __restrict__ outQ0, unsigned char* __restrict__ outQ1,
       float* __restrict__ outF0, float* __restrict__ outF1,
       const float* __restrict__ hh, const float* __restrict__ cf)
{
    const int u = blockIdx.x * 8 + (threadIdx.x >> 5);
    const int lane = threadIdx.x & 31;
    const bool s1 = (u >= BN_);
    const int r = s1 ? u - BN_ : u;
    const int* rp  = s1 ? rp1  : rp0;
    const int* col = s1 ? col1 : col0;
    const float* av = s1 ? av1 : av0;
    const unsigned char* zb = (s1 ? Z1 : Z0) + (size_t)(r & ~(N_ - 1)) * D_;
    const int rs = rp[r], re = rp[r + 1];
    const int off = lane * 4;

    float4 acc = make_float4(0.f, 0.f, 0.f, 0.f);
    int e = rs;
    for (; e + 4 <= re; e += 4) {
        const int   j0 = col[e],   j1 = col[e+1], j2 = col[e+2], j3 = col[e+3];
        const float a0 = av[e],    a1 = av[e+1],  a2 = av[e+2],  a3 = av[e+3];
        const float4 z0 = ldq4(zb + (size_t)j0 * D_ + off);
        const float4 z1 = ldq4(zb + (size_t)j1 * D_ + off);
        const float4 z2 = ldq4(zb + (size_t)j2 * D_ + off);
        const float4 z3 = ldq4(zb + (size_t)j3 * D_ + off);
        acc.x += a0*z0.x + a1*z1.x + a2*z2.x + a3*z3.x;
        acc.y += a0*z0.y + a1*z1.y + a2*z2.y + a3*z3.y;
        acc.z += a0*z0.z + a1*z1.z + a2*z2.z + a3*z3.z;
        acc.w += a0*z0.w + a1*z1.w + a2*z2.w + a3*z3.w;
    }
    for (; e < re; ++e) {
        const int j = col[e];
        const float a = av[e];
        const float4 zv = ldq4(zb + (size_t)j * D_ + off);
        acc.x += a*zv.x; acc.y += a*zv.y; acc.z += a*zv.z; acc.w += a*zv.w;
    }

    acc.x = fmaxf(acc.x, 0.f); acc.y = fmaxf(acc.y, 0.f);
    acc.z = fmaxf(acc.z, 0.f); acc.w = fmaxf(acc.w, 0.f);
    const size_t go = (size_t)r * D_ + off;

    if (EPI == 0) {
        stz4((s1 ? outZ1 : outZ0) + go, acc);
    } else {
        const float c = cf[u], om = 1.f - c;
        const float4 hv = *(const float4*)(hh + go);
        float4 o;
        o.x = c*hv.x + om*acc.x; o.y = c*hv.y + om*acc.y;
        o.z = c*hv.z + om*acc.z; o.w = c*hv.w + om*acc.w;
        if (EPI == 1) stq4((s1 ? outQ1 : outQ0) + go, o);
        else          *(float4*)((s1 ? outF1 : outF0) + go) = o;
    }
}

// ===== gate + hop1 for both branches (az post-relu bf16) =====
// NH1: h_out = (c1*hh+(1-c1)*az1) - (c0*hh+(1-c0)*az0)   [fp32]
// else: write bf16 blend -> fp8 z stage (q0/q1); cf stored.
template<bool NH1>
__global__ void __launch_bounds__(256)
gatehop_k(const float* __restrict__ hh, const bf16* __restrict__ az0,
          const bf16* __restrict__ az1, const float* __restrict__ gw,
          const float* __restrict__ gb, float* __restrict__ cf,
          float* __restrict__ hout,
          unsigned char* __restrict__ q0, unsigned char* __restrict__ q1)
{
    const int r = blockIdx.x * 8 + (threadIdx.x >> 5);
    const int lane = threadIdx.x & 31;
    if (r >= BN_) return;
    const size_t o = (size_t)r * D_ + lane * 4;
    const float4 hv = *(const float4*)(hh + o);
    const float4 z0 = ldz4(az0 + o);
    const float4 z1 = ldz4(az1 + o);
    const float4 g1 = *(const float4*)(gw + lane * 4);
    const float4 g2 = *(const float4*)(gw + D_ + lane * 4);
    const float t = hv.x*g1.x + hv.y*g1.y + hv.z*g1.z + hv.w*g1.w;
    float s0 = t + z0.x*g2.x + z0.y*g2.y + z0.z*g2.z + z0.w*g2.w;
    float s1 = t + z1.x*g2.x + z1.y*g2.y + z1.z*g2.z + z1.w*g2.w;
#pragma unroll
    for (int off = 16; off; off >>= 1) {
        s0 += __shfl_xor_sync(0xFFFFFFFFu, s0, off);
        s1 += __shfl_xor_sync(0xFFFFFFFFu, s1, off);
    }
    const float gbv = gb[0];
    const float c0 = 1.f / (1.f + __expf(-(s0 + gbv)));
    const float c1 = 1.f / (1.f + __expf(-(s1 + gbv)));
    if (NH1) {
        float4 ov;
        ov.x = (c1*hv.x + (1.f-c1)*z1.x) - (c0*hv.x + (1.f-c0)*z0.x);
        ov.y = (c1*hv.y + (1.f-c1)*z1.y) - (c0*hv.y + (1.f-c0)*z0.y);
        ov.z = (c1*hv.z + (1.f-c1)*z1.z) - (c0*hv.z + (1.f-c0)*z0.z);
        ov.w = (c1*hv.w + (1.f-c1)*z1.w) - (c0*hv.w + (1.f-c0)*z0.w);
        *(float4*)(hout + o) = ov;
    } else {
        float4 w0, w1;
        w0.x = c0*hv.x + (1.f-c0)*z0.x; w0.y = c0*hv.y + (1.f-c0)*z0.y;
        w0.z = c0*hv.z + (1.f-c0)*z0.z; w0.w = c0*hv.w + (1.f-c0)*z0.w;
        w1.x = c1*hv.x + (1.f-c1)*z1.x; w1.y = c1*hv.y + (1.f-c1)*z1.y;
        w1.z = c1*hv.z + (1.f-c1)*z1.z; w1.w = c1*hv.w + (1.f-c1)*z1.w;
        stq4(q0 + o, w0);
        stq4(q1 + o, w1);
        if (lane == 0) { cf[r] = c0; cf[BN_ + r] = c1; }
    }
}

// ============ tail ============
__global__ void sub_k(const float* __restrict__ z2, const float* __restrict__ z1,
                      float* __restrict__ o)
{
    const size_t i = (size_t)blockIdx.x * blockDim.x + threadIdx.x;
    float4 a = ((const float4*)z2)[i];
    float4 b = ((const float4*)z1)[i];
    ((float4*)o)[i] = make_float4(a.x-b.x, a.y-b.y, a.z-b.z, a.w-b.w);
}

__global__ void pool_k(const float* __restrict__ h, const float* __restrict__ valid,
                       float* __restrict__ pooled)
{
    const int b = blockIdx.x, d = threadIdx.x;
    float s = 0.f, vs = 0.f;
#pragma unroll 8
    for (int n = 0; n < N_; n++) {
        float v = valid[b * N_ + n];
        s += h[((size_t)b * N_ + n) * D_ + d] * v;
        vs += v;
    }
    pooled[b * D_ + d] = s / vs;
}

__global__ void mlp_k(const float* __restrict__ pooled,
                      const float* __restrict__ w0, const float* __restrict__ b0,
                      const float* __restrict__ w1, const float* __restrict__ b1,
                      const float* __restrict__ w2, const float* __restrict__ b2,
                      const float* __restrict__ w3, const float* __restrict__ b3,
                      float* __restrict__ out)
{
    __shared__ float a0[128], a1[128], red[4];
    const int b = blockIdx.x, t = threadIdx.x;
    a0[t] = pooled[b * 128 + t];
    __syncthreads();
    float s = 0.f;
    for (int i = 0; i < 128; i++) s += a0[i] * w0[t*128+i];
    a1[t] = fmaxf(s + b0[t], 0.f);
    __syncthreads();
    s = 0.f;
    for (int i = 0; i < 128; i++) s += a1[i] * w1[t*128+i];
    a0[t] = fmaxf(s + b1[t], 0.f);
    __syncthreads();
    s = 0.f;
    for (int i = 0; i < 128; i++) s += a0[i] * w2[t*128+i];
    a1[t] = fmaxf(s + b2[t], 0.f);
    __syncthreads();
    float p = a1[t] * w3[t];
    for (int o = 16; o; o >>= 1) p += __shfl_xor_sync(0xFFFFFFFFu, p, o);
    if ((t & 31) == 0) red[t >> 5] = p;
    __syncthreads();
    if (t == 0) {
        float tot = red[0] + red[1] + red[2] + red[3] + b3[0];
        out[b] = 1.f / (1.f + expf(-tot));
    }
}

extern "C" void kernel_launch(void* const* d_in, const int* in_sizes, int n_in,
                              void* d_out, int out_size)
{
    const float* x       = (const float*)d_in[0];
    const float* adj1    = (const float*)d_in[1];
    const float* adj2    = (const float*)d_in[2];
    const float* valid   = (const float*)d_in[3];
    const float* embede_w= (const float*)d_in[4];
    const float* gW      = (const float*)d_in[5];
    const float* gb      = (const float*)d_in[6];
    const float* gA      = (const float*)d_in[7];
    const float* gate_w  = (const float*)d_in[8];
    const float* gate_b  = (const float*)d_in[9];
    const float* fc0_w   = (const float*)d_in[10];
    const float* fc0_b   = (const float*)d_in[11];
    const float* fc1_w   = (const float*)d_in[12];
    const float* fc1_b   = (const float*)d_in[13];
    const float* fc2_w   = (const float*)d_in[14];
    const float* fc2_b   = (const float*)d_in[15];
    const float* fc3_w   = (const float*)d_in[16];
    const float* fc3_b   = (const float*)d_in[17];
    float* out = (float*)d_out;

    float *p_h, *p_hh, *p_hA, *p_zA, *p_zC, *p_cf, *p_pool, *p_invs;
    bf16 *p_hhb, *p_hAb, *p_azb;
    unsigned char *p_hh8, *p_z8;
    float *p_ev, *p_av;
    int *p_rp, *p_col, *p_mir, *p_us;
    cudaGetSymbolAddress((void**)&p_h,   g_h);
    cudaGetSymbolAddress((void**)&p_hh,  g_hh);
    cudaGetSymbolAddress((void**)&p_hA,  g_hA);
    cudaGetSymbolAddress((void**)&p_hhb, g_hhb);
    cudaGetSymbolAddress((void**)&p_hAb, g_hAb);
    cudaGetSymbolAddress((void**)&p_hh8, g_hh8);
    cudaGetSymbolAddress((void**)&p_z8,  g_z8);
    cudaGetSymbolAddress((void**)&p_azb, g_azb);
    cudaGetSymbolAddress((void**)&p_zA,  g_zA);
    cudaGetSymbolAddress((void**)&p_zC,  g_zC);
    cudaGetSymbolAddress((void**)&p_cf,  g_cf);
    cudaGetSymbolAddress((void**)&p_pool,g_pool);
    cudaGetSymbolAddress((void**)&p_ev,  g_ev);
    cudaGetSymbolAddress((void**)&p_av,  g_av);
    cudaGetSymbolAddress((void**)&p_invs,g_invs);
    cudaGetSymbolAddress((void**)&p_rp,  g_rowptr);
    cudaGetSymbolAddress((void**)&p_col, g_col);
    cudaGetSymbolAddress((void**)&p_mir, g_mir);
    cudaGetSymbolAddress((void**)&p_us,  g_us);

    const int NHOPS[4] = {1, 2, 3, 4};
    int* rp_[2]   = {p_rp,  p_rp  + (BN_ + 1)};
    int* col_[2]  = {p_col, p_col + EMAX};
    int* mir_[2]  = {p_mir, p_mir + EMAX};
    int* us_[2]   = {p_us,  p_us  + BN_};
    float* ev_[2] = {p_ev,  p_ev  + EMAX};
    float* av_[2] = {p_av,  p_av  + EMAX};
    bf16* azb_[2] = {p_azb, p_azb + (size_t)BN_*D_};
    unsigned char* z8_[2][2] =
        {{p_z8,                    p_z8 + (size_t)BN_*D_},
         {p_z8 + 2*(size_t)BN_*D_, p_z8 + 3*(size_t)BN_*D_}};

    deg_k   <<<dim3(2048,2), 256>>>(adj1, adj2, rp_[0], rp_[1]);
    scan_k  <<<2, 1024>>>(rp_[0], rp_[1]);
    fill_k  <<<dim3(2048,2), 256>>>(adj1, adj2, rp_[0], rp_[1], col_[0], col_[1]);
    mirror_k<<<dim3(2048,2), 256>>>(rp_[0], col_[0], mir_[0], us_[0],
                                    rp_[1], col_[1], mir_[1], us_[1]);

    sgemm_e_k<<<256, 256>>>(x, embede_w, p_h, D_);

    for (int k = 0; k < L_; k++) {
        const float* Wk  = gW + (size_t)k * D_ * D_;
        const float* bk  = gb + (size_t)k * D_;
        const float* Ak  = gA + (size_t)k * D_ * D_;
        const float* gwk = gate_w + (size_t)k * 2 * D_;
        const float* gbk = gate_b + k;
        const int nhop = NHOPS[k];

        hhA_k<<<256, 256>>>(p_h, Wk, Ak, bk, p_hh, p_hhb, p_hh8, p_hA, p_hAb);

        elog2_k<<<dim3(N_, B_, 2), 128>>>(p_hh, p_hA, p_hhb, p_hAb,
            rp_[0], col_[0], mir_[0], us_[0], ev_[0],
            rp_[1], col_[1], mir_[1], us_[1], ev_[1]);
        stats2_k<<<4096, 256>>>(rp_[0], ev_[0], rp_[1], ev_[1], p_invs);
        fold2_k <<<4096, 256>>>(rp_[0], col_[0], ev_[0], av_[0],
                                rp_[1], col_[1], ev_[1], av_[1], p_invs);

        // first hop: az = relu(att @ hh) (fp8 gather of hh8), both branches
        spmm_k<0><<<4096, 256>>>(rp_[0], col_[0], av_[0],
            rp_[1], col_[1], av_[1], p_hh8, p_hh8,
            azb_[0], azb_[1], nullptr, nullptr, nullptr, nullptr,
            p_hh, p_cf);

        if (nhop == 1) {
            gatehop_k<true><<<2048, 256>>>(p_hh, azb_[0], azb_[1],
                gwk, gbk, p_cf, p_h, nullptr, nullptr);
        } else {
            gatehop_k<false><<<2048, 256>>>(p_hh, azb_[0], azb_[1],
                gwk, gbk, p_cf, nullptr, z8_[0][0], z8_[1][0]);
            int cur = 0;
            for (int hp = 2; hp < nhop; hp++) {
                spmm_k<1><<<4096, 256>>>(rp_[0], col_[0], av_[0],
                    rp_[1], col_[1], av_[1],
                    z8_[0][cur], z8_[1][cur],
                    nullptr, nullptr, z8_[0][cur^1], z8_[1][cur^1],
                    nullptr, nullptr, p_hh, p_cf);
                cur ^= 1;
            }
            spmm_k<2><<<4096, 256>>>(rp_[0], col_[0], av_[0],
                rp_[1], col_[1], av_[1],
                z8_[0][cur], z8_[1][cur],
                nullptr, nullptr, nullptr, nullptr, p_zA, p_zC,
                p_hh, p_cf);
            sub_k<<<2048, 256>>>(p_zC, p_zA, p_h);
        }
    }

    pool_k<<<B_, D_>>>(p_h, valid, p_pool);
    mlp_k<<<B_, D_>>>(p_pool, fc0_w, fc0_b, fc1_w, fc1_b,
                      fc2_w, fc2_b, fc3_w, fc3_b, out);
}